// round 4
// baseline (speedup 1.0000x reference)
#include <cuda_runtime.h>
#include <math.h>

#define NF       13776
#define KMAX     8
#define NBLOCKS  148
#define NTHREADS 1024
#define WPB      (NTHREADS / 32)            // 32 warps per block
#define NWARPS   (NBLOCKS * WPB)            // 4736
#define NITEMS   (NF * KMAX * 2)            // 220416 narrow-phase work items

// ---------------------------------------------------------------------------
// Scratch (__device__ globals — allocation-free)
// ---------------------------------------------------------------------------
__device__ float4 d_tri4[NF * 3];   // per-face vertices (w=0)
__device__ float4 d_aabb[NF * 2];   // [2f]=bbmin, [2f+1]=bbmax
__device__ int4   d_fidx[NF];       // 3 vertex ids per face
__device__ int    d_pairs[NF * KMAX]; // intruder index per slot, -1 = empty
__device__ float  d_part[NBLOCKS];
__device__ unsigned d_barArrive = 0;
__device__ unsigned d_barGen    = 0; // monotonic across graph replays

// ---------------------------------------------------------------------------
// Grid-wide barrier (generation counter; 148 co-resident blocks, 1/SM).
// ---------------------------------------------------------------------------
__device__ __forceinline__ void grid_barrier() {
    __threadfence();
    __syncthreads();
    if (threadIdx.x == 0) {
        unsigned gen = *(volatile unsigned*)&d_barGen;
        unsigned t   = atomicAdd(&d_barArrive, 1u);
        if (t == NBLOCKS - 1) {
            atomicExch(&d_barArrive, 0u);
            __threadfence();
            atomicAdd(&d_barGen, 1u);
        } else {
            while (*(volatile unsigned*)&d_barGen == gen) { }
        }
        __threadfence();
    }
    __syncthreads();
}

// ---------------------------------------------------------------------------
// Cone-field penalty (SIGMA=0.5, PENALIZE_OUTSIDE, phi^2 form) of src tri
// (s0,s1,s2) evaluated at the 3 vertices (p0,p1,p2).
// ---------------------------------------------------------------------------
__device__ __forceinline__ float cone_pen(float4 s0, float4 s1, float4 s2,
                                          float4 p0, float4 p1, float4 p2) {
    float e0x = s1.x - s0.x, e0y = s1.y - s0.y, e0z = s1.z - s0.z;
    float e1x = s2.x - s0.x, e1y = s2.y - s0.y, e1z = s2.z - s0.z;
    float nx = e0y * e1z - e0z * e1y;
    float ny = e0z * e1x - e0x * e1z;
    float nz = e0x * e1y - e0y * e1x;
    float l  = sqrtf(nx * nx + ny * ny + nz * nz);
    float inv = 1.0f / (l + 1e-8f);
    nx *= inv; ny *= inv; nz *= inv;
    float cx = (s0.x + s1.x + s2.x) * (1.0f / 3.0f);
    float cy = (s0.y + s1.y + s2.y) * (1.0f / 3.0f);
    float cz = (s0.z + s1.z + s2.z) * (1.0f / 3.0f);
    float acc = 0.0f;
#pragma unroll
    for (int k = 0; k < 3; k++) {
        float4 p = (k == 0) ? p0 : ((k == 1) ? p1 : p2);
        float ux = p.x - cx, uy = p.y - cy, uz = p.z - cz;
        float h  = ux * nx + uy * ny + uz * nz;
        float wx = ux - h * nx, wy = uy - h * ny, wz = uz - h * nz;
        float r  = sqrtf(wx * wx + wy * wy + wz * wz);
        float radial = fmaxf(1.0f - 2.0f * r, 0.0f);
        float depth  = fmaxf(-h, 0.0f) + fmaxf(h, 0.0f) * __expf(-2.0f * h);
        float phi = radial * depth;
        acc += phi * phi;
    }
    return acc;
}

// ---------------------------------------------------------------------------
// Single fused kernel:
//   P1 gather/AABB -> bar -> PA broad-phase pair build -> bar ->
//   PB dense narrow phase (thread per (pair,dir)) -> bar -> reduce
// ---------------------------------------------------------------------------
__global__ __launch_bounds__(NTHREADS, 1)
void fused_kernel(const float* __restrict__ verts,
                  const int*  __restrict__ faces,
                  float* __restrict__ out) {
    const int tid  = threadIdx.x;
    const int lane = tid & 31;
    const int wid  = tid >> 5;

    // ---------------- Phase 1: gather + AABB (one face per thread) ----------
    for (int f = blockIdx.x * NTHREADS + tid; f < NF; f += NBLOCKS * NTHREADS) {
        int i0 = faces[3 * f + 0];
        int i1 = faces[3 * f + 1];
        int i2 = faces[3 * f + 2];
        float x0 = verts[3 * i0], y0 = verts[3 * i0 + 1], z0 = verts[3 * i0 + 2];
        float x1 = verts[3 * i1], y1 = verts[3 * i1 + 1], z1 = verts[3 * i1 + 2];
        float x2 = verts[3 * i2], y2 = verts[3 * i2 + 1], z2 = verts[3 * i2 + 2];
        d_tri4[3 * f + 0] = make_float4(x0, y0, z0, 0.f);
        d_tri4[3 * f + 1] = make_float4(x1, y1, z1, 0.f);
        d_tri4[3 * f + 2] = make_float4(x2, y2, z2, 0.f);
        d_fidx[f] = make_int4(i0, i1, i2, 0);
        d_aabb[2 * f + 0] = make_float4(fminf(x0, fminf(x1, x2)),
                                        fminf(y0, fminf(y1, y2)),
                                        fminf(z0, fminf(z1, z2)), 0.f);
        d_aabb[2 * f + 1] = make_float4(fmaxf(x0, fmaxf(x1, x2)),
                                        fmaxf(y0, fmaxf(y1, y2)),
                                        fmaxf(z0, fmaxf(z1, z2)), 0.f);
    }

    grid_barrier();

    // ---------------- Phase A: warp-per-face broad phase --------------------
    {
        const int gwarp = blockIdx.x * WPB + wid;
        for (int f = gwarp; f < NF; f += NWARPS) {
            const float4 fmn = d_aabb[2 * f + 0];
            const float4 fmx = d_aabb[2 * f + 1];
            const int4   fid = d_fidx[f];

            int found = 0;
            int myIntr = -1;
            for (int base = 0; base < NF && found < KMAX; base += 32) {
                int j = base + lane;
                bool v = false;
                if (j < NF) {
                    float4 jmn = d_aabb[2 * j + 0];
                    float4 jmx = d_aabb[2 * j + 1];
                    bool ov = (fmn.x <= jmx.x) & (jmn.x <= fmx.x)
                            & (fmn.y <= jmx.y) & (jmn.y <= fmx.y)
                            & (fmn.z <= jmx.z) & (jmn.z <= fmx.z);
                    if (ov) {
                        int4 jid = d_fidx[j];
                        bool share = (jid.x == fid.x) | (jid.x == fid.y) | (jid.x == fid.z)
                                   | (jid.y == fid.x) | (jid.y == fid.y) | (jid.y == fid.z)
                                   | (jid.z == fid.x) | (jid.z == fid.y) | (jid.z == fid.z);
                        v = !share;
                    }
                }
                unsigned m = __ballot_sync(0xffffffffu, v);
                while (m && found < KMAX) {
                    int b = __ffs(m) - 1;
                    if (lane == found) myIntr = base + b;
                    found++;
                    m &= (m - 1);
                }
            }
            if (lane < KMAX)
                d_pairs[f * KMAX + lane] = (lane < found) ? myIntr : -1;
        }
    }

    grid_barrier();

    // ---------------- Phase B: dense narrow phase ---------------------------
    // item = (face f, slot k, dir). All lanes active; fixed mapping => deterministic.
    float pen = 0.0f;
    for (int it = blockIdx.x * NTHREADS + tid; it < NITEMS; it += NBLOCKS * NTHREADS) {
        int pairIdx = it >> 1;
        int dir     = it & 1;
        int f       = pairIdx >> 3;           // KMAX = 8
        int intr    = d_pairs[pairIdx];
        if (intr >= 0) {
            float4 a0 = d_tri4[3 * f + 0];
            float4 a1 = d_tri4[3 * f + 1];
            float4 a2 = d_tri4[3 * f + 2];
            float4 b0 = d_tri4[3 * intr + 0];
            float4 b1 = d_tri4[3 * intr + 1];
            float4 b2 = d_tri4[3 * intr + 2];
            // dir 0: field of receiver evaluated at intruder verts; dir 1: reverse
            pen += dir ? cone_pen(b0, b1, b2, a0, a1, a2)
                       : cone_pen(a0, a1, a2, b0, b1, b2);
        }
    }

    // warp reduce (fixed order -> deterministic)
    __shared__ float s_warp[WPB];
#pragma unroll
    for (int o = 16; o; o >>= 1)
        pen += __shfl_down_sync(0xffffffffu, pen, o);
    if (lane == 0) s_warp[wid] = pen;
    __syncthreads();
    if (tid == 0) {
        float s = 0.0f;
#pragma unroll
        for (int w = 0; w < WPB; w++) s += s_warp[w];
        d_part[blockIdx.x] = s;
    }

    grid_barrier();

    // ---------------- Final deterministic reduce ----------------------------
    if (blockIdx.x == 0 && tid == 0) {
        float s = 0.0f;
#pragma unroll 4
        for (int i = 0; i < NBLOCKS; i++) s += d_part[i];
        out[0] = s;
    }
}

extern "C" void kernel_launch(void* const* d_in, const int* in_sizes, int n_in,
                              void* d_out, int out_size) {
    const float* verts = (const float*)d_in[0];  // [1,6890,3] float32
    const int*   faces = (const int*)d_in[1];    // [13776*3] int32
    (void)in_sizes; (void)n_in; (void)out_size;

    fused_kernel<<<NBLOCKS, NTHREADS>>>(verts, faces, (float*)d_out);
}

// round 5
// speedup vs baseline: 1.5185x; 1.5185x over previous
#include <cuda_runtime.h>
#include <math.h>

#define NF     13776
#define KMAX   8
#define NPAIRS (NF * KMAX)
#define NITEMS (NPAIRS * 2)            // 220416 narrow-phase items
#define NARROW_THREADS 256
#define NARROW_BLOCKS  ((NITEMS + NARROW_THREADS - 1) / NARROW_THREADS)  // 861

// ---------------------------------------------------------------------------
// Scratch (__device__ globals — allocation-free)
// ---------------------------------------------------------------------------
__device__ float4 d_tri4[NF * 3];     // per-face vertices (w=0)
__device__ float4 d_aabb[NF * 2];     // [2f]=bbmin, [2f+1]=bbmax
__device__ int4   d_fidx[NF];         // 3 vertex ids per face
__device__ int    d_pairs[NPAIRS];    // intruder per slot, -1 = empty
__device__ float  d_part[NARROW_BLOCKS];

// ---------------------------------------------------------------------------
// K1: gather triangles, face ids, AABBs
// ---------------------------------------------------------------------------
__global__ void prep_kernel(const float* __restrict__ verts,
                            const int*  __restrict__ faces) {
    int f = blockIdx.x * blockDim.x + threadIdx.x;
    if (f >= NF) return;
    int i0 = __ldg(&faces[3 * f + 0]);
    int i1 = __ldg(&faces[3 * f + 1]);
    int i2 = __ldg(&faces[3 * f + 2]);
    float x0 = __ldg(&verts[3 * i0]), y0 = __ldg(&verts[3 * i0 + 1]), z0 = __ldg(&verts[3 * i0 + 2]);
    float x1 = __ldg(&verts[3 * i1]), y1 = __ldg(&verts[3 * i1 + 1]), z1 = __ldg(&verts[3 * i1 + 2]);
    float x2 = __ldg(&verts[3 * i2]), y2 = __ldg(&verts[3 * i2 + 1]), z2 = __ldg(&verts[3 * i2 + 2]);
    d_tri4[3 * f + 0] = make_float4(x0, y0, z0, 0.f);
    d_tri4[3 * f + 1] = make_float4(x1, y1, z1, 0.f);
    d_tri4[3 * f + 2] = make_float4(x2, y2, z2, 0.f);
    d_fidx[f] = make_int4(i0, i1, i2, 0);
    d_aabb[2 * f + 0] = make_float4(fminf(x0, fminf(x1, x2)),
                                    fminf(y0, fminf(y1, y2)),
                                    fminf(z0, fminf(z1, z2)), 0.f);
    d_aabb[2 * f + 1] = make_float4(fmaxf(x0, fmaxf(x1, x2)),
                                    fmaxf(y0, fmaxf(y1, y2)),
                                    fmaxf(z0, fmaxf(z1, z2)), 0.f);
}

// ---------------------------------------------------------------------------
// K2: warp-per-face broad phase. First <=8 valid intruders in ascending order
// (== stable top_k of the 0/1 validity row). Early exit after slots fill
// (nearly always the first 32-candidate window for this data).
// ---------------------------------------------------------------------------
__global__ void broad_kernel() {
    const int lane = threadIdx.x & 31;
    const int wid  = threadIdx.x >> 5;
    const int f    = blockIdx.x * (blockDim.x >> 5) + wid;
    if (f >= NF) return;

    const float4 fmn = d_aabb[2 * f + 0];
    const float4 fmx = d_aabb[2 * f + 1];
    const int4   fid = d_fidx[f];

    int found = 0;
    int myIntr = -1;
    for (int base = 0; base < NF && found < KMAX; base += 32) {
        int j = base + lane;
        bool v = false;
        if (j < NF) {
            float4 jmn = d_aabb[2 * j + 0];
            float4 jmx = d_aabb[2 * j + 1];
            bool ov = (fmn.x <= jmx.x) & (jmn.x <= fmx.x)
                    & (fmn.y <= jmx.y) & (jmn.y <= fmx.y)
                    & (fmn.z <= jmx.z) & (jmn.z <= fmx.z);
            if (ov) {
                int4 jid = d_fidx[j];
                bool share = (jid.x == fid.x) | (jid.x == fid.y) | (jid.x == fid.z)
                           | (jid.y == fid.x) | (jid.y == fid.y) | (jid.y == fid.z)
                           | (jid.z == fid.x) | (jid.z == fid.y) | (jid.z == fid.z);
                v = !share;
            }
        }
        unsigned m = __ballot_sync(0xffffffffu, v);
        while (m && found < KMAX) {
            int b = __ffs(m) - 1;
            if (lane == found) myIntr = base + b;
            found++;
            m &= (m - 1);
        }
    }
    if (lane < KMAX)
        d_pairs[f * KMAX + lane] = (lane < found) ? myIntr : -1;
}

// ---------------------------------------------------------------------------
// Cone-field penalty (SIGMA=0.5, PENALIZE_OUTSIDE, phi^2).
// ---------------------------------------------------------------------------
__device__ __forceinline__ float cone_pen(float4 s0, float4 s1, float4 s2,
                                          float4 p0, float4 p1, float4 p2) {
    float e0x = s1.x - s0.x, e0y = s1.y - s0.y, e0z = s1.z - s0.z;
    float e1x = s2.x - s0.x, e1y = s2.y - s0.y, e1z = s2.z - s0.z;
    float nx = e0y * e1z - e0z * e1y;
    float ny = e0z * e1x - e0x * e1z;
    float nz = e0x * e1y - e0y * e1x;
    float l  = sqrtf(nx * nx + ny * ny + nz * nz);
    float inv = 1.0f / (l + 1e-8f);
    nx *= inv; ny *= inv; nz *= inv;
    float cx = (s0.x + s1.x + s2.x) * (1.0f / 3.0f);
    float cy = (s0.y + s1.y + s2.y) * (1.0f / 3.0f);
    float cz = (s0.z + s1.z + s2.z) * (1.0f / 3.0f);
    float acc = 0.0f;
#pragma unroll
    for (int k = 0; k < 3; k++) {
        float4 p = (k == 0) ? p0 : ((k == 1) ? p1 : p2);
        float ux = p.x - cx, uy = p.y - cy, uz = p.z - cz;
        float h  = ux * nx + uy * ny + uz * nz;
        float wx = ux - h * nx, wy = uy - h * ny, wz = uz - h * nz;
        float r  = sqrtf(wx * wx + wy * wy + wz * wz);
        float radial = fmaxf(1.0f - 2.0f * r, 0.0f);
        float depth  = fmaxf(-h, 0.0f) + fmaxf(h, 0.0f) * __expf(-2.0f * h);
        float phi = radial * depth;
        acc += phi * phi;
    }
    return acc;
}

// ---------------------------------------------------------------------------
// K3: dense narrow phase — one thread per (pair, direction). All lanes busy.
// Block-level deterministic partial sums.
// ---------------------------------------------------------------------------
__global__ void narrow_kernel() {
    const int it   = blockIdx.x * NARROW_THREADS + threadIdx.x;
    const int lane = threadIdx.x & 31;
    const int wid  = threadIdx.x >> 5;

    float pen = 0.0f;
    if (it < NITEMS) {
        int pairIdx = it >> 1;
        int dir     = it & 1;
        int f       = pairIdx >> 3;          // KMAX = 8
        int intr    = d_pairs[pairIdx];
        if (intr >= 0) {
            float4 a0 = d_tri4[3 * f + 0];
            float4 a1 = d_tri4[3 * f + 1];
            float4 a2 = d_tri4[3 * f + 2];
            float4 b0 = d_tri4[3 * intr + 0];
            float4 b1 = d_tri4[3 * intr + 1];
            float4 b2 = d_tri4[3 * intr + 2];
            pen = dir ? cone_pen(b0, b1, b2, a0, a1, a2)
                      : cone_pen(a0, a1, a2, b0, b1, b2);
        }
    }

    __shared__ float s_warp[NARROW_THREADS / 32];
#pragma unroll
    for (int o = 16; o; o >>= 1)
        pen += __shfl_down_sync(0xffffffffu, pen, o);
    if (lane == 0) s_warp[wid] = pen;
    __syncthreads();
    if (threadIdx.x == 0) {
        float s = 0.0f;
#pragma unroll
        for (int w = 0; w < NARROW_THREADS / 32; w++) s += s_warp[w];
        d_part[blockIdx.x] = s;
    }
}

// ---------------------------------------------------------------------------
// K4: final deterministic reduce
// ---------------------------------------------------------------------------
__global__ void reduce_kernel(float* __restrict__ out) {
    __shared__ float s[256];
    float acc = 0.0f;
    // fixed-stride accumulation -> deterministic
    for (int i = threadIdx.x; i < NARROW_BLOCKS; i += 256) acc += d_part[i];
    s[threadIdx.x] = acc;
    __syncthreads();
    for (int st = 128; st; st >>= 1) {
        if (threadIdx.x < st) s[threadIdx.x] += s[threadIdx.x + st];
        __syncthreads();
    }
    if (threadIdx.x == 0) out[0] = s[0];
}

extern "C" void kernel_launch(void* const* d_in, const int* in_sizes, int n_in,
                              void* d_out, int out_size) {
    const float* verts = (const float*)d_in[0];  // [1,6890,3] float32
    const int*   faces = (const int*)d_in[1];    // [13776*3] int32
    (void)in_sizes; (void)n_in; (void)out_size;

    prep_kernel<<<(NF + 127) / 128, 128>>>(verts, faces);
    broad_kernel<<<(NF + 7) / 8, 256>>>();
    narrow_kernel<<<NARROW_BLOCKS, NARROW_THREADS>>>();
    reduce_kernel<<<1, 256>>>((float*)d_out);
}